// round 3
// baseline (speedup 1.0000x reference)
#include <cuda_runtime.h>
#include <cuda_bf16.h>

// DynamicPatchAggregator — gather formulation, float4 along w, channel split
// across threadIdx.z to halve per-thread register pressure and raise occupancy.
// vol=192^3, patch=96^3, stride=48 -> starts {0,48,96}, 27 patches, C=2.
// Coverage is complete -> upsampled global branch contributes 0; skip it.

#define VOL 192
#define PATCH 96
#define STRIDE 48
#define CH_STRIDE (PATCH*PATCH*PATCH)          // 884736
#define PATCH_STRIDE (2*CH_STRIDE)             // per-k stride (C=2)
#define OUT_CH_STRIDE (VOL*VOL*VOL)            // 7077888

struct AxisInfo {
    int   si[2];
    int   loc[2];
    float g[2];
    int   n;
    float gsum;
};

__device__ __forceinline__ AxisInfo axis_info(int x) {
    AxisInfo a;
    int lo = (x >= PATCH) ? ((x - (PATCH - 1) + (STRIDE - 1)) / STRIDE) : 0;
    int hi = x / STRIDE; if (hi > 2) hi = 2;
    a.n = hi - lo + 1;
    a.gsum = 0.f;
    #pragma unroll
    for (int i = 0; i < 2; i++) {
        int si = lo + i;
        if (i < a.n) {
            int l = x - si * STRIDE;
            float t = (float)(l - 48) * (1.0f / 12.0f);
            float g = __expf(-0.5f * t * t);
            a.si[i] = si; a.loc[i] = l; a.g[i] = g;
            a.gsum += g;
        } else {
            a.si[i] = 0; a.loc[i] = 0; a.g[i] = 0.f;
        }
    }
    return a;
}

__global__ __launch_bounds__(192, 7) void agg_kernel_v4c(const float* __restrict__ patch,
                                                         float* __restrict__ out) {
    const int w0 = threadIdx.x * 4;              // 0,4,...,188
    const int c  = threadIdx.z;                  // channel 0/1
    const int h  = blockIdx.x * 2 + threadIdx.y; // 0..191
    const int d  = blockIdx.y;                   // 0..191

    AxisInfo ad = axis_info(d);
    AxisInfo ah = axis_info(h);

    // w-axis info for the 4-wide group (uniform covering set, 4-aligned locs)
    int wlo = (w0 >= PATCH) ? ((w0 - (PATCH - 1) + (STRIDE - 1)) / STRIDE) : 0;
    int whi = w0 / STRIDE; if (whi > 2) whi = 2;
    const int wn = whi - wlo + 1;

    int   wloc0[2];
    int   wsi[2];
    float gw[2][4];
    float gsum_w[4] = {0.f, 0.f, 0.f, 0.f};
    #pragma unroll
    for (int i = 0; i < 2; i++) {
        int si = wlo + i;
        if (i < wn) {
            int l0 = w0 - si * STRIDE;
            wsi[i] = si; wloc0[i] = l0;
            #pragma unroll
            for (int j = 0; j < 4; j++) {
                float t = (float)(l0 + j - 48) * (1.0f / 12.0f);
                float g = __expf(-0.5f * t * t);
                gw[i][j] = g;
                gsum_w[j] += g;
            }
        } else {
            wsi[i] = 0; wloc0[i] = 0;
            #pragma unroll
            for (int j = 0; j < 4; j++) gw[i][j] = 0.f;
        }
    }

    const float* __restrict__ p = patch + c * CH_STRIDE;

    float4 acc = make_float4(0.f, 0.f, 0.f, 0.f);

    #pragma unroll
    for (int id = 0; id < 2; id++) {
        if (id >= ad.n) break;
        const int ld = ad.loc[id];
        #pragma unroll
        for (int ih = 0; ih < 2; ih++) {
            if (ih >= ah.n) break;
            const int lh = ah.loc[ih];
            const float gdh = ad.g[id] * ah.g[ih];
            const int kdh = (ad.si[id] * 3 + ah.si[ih]) * 3;
            const int off_dh = (ld * PATCH + lh) * PATCH;
            #pragma unroll
            for (int iw = 0; iw < 2; iw++) {
                if (iw >= wn) break;
                const int k = kdh + wsi[iw];
                const int base = k * PATCH_STRIDE + off_dh + wloc0[iw];
                const float4 v = *reinterpret_cast<const float4*>(p + base);
                acc.x = fmaf(gdh * gw[iw][0], v.x, acc.x);
                acc.y = fmaf(gdh * gw[iw][1], v.y, acc.y);
                acc.z = fmaf(gdh * gw[iw][2], v.z, acc.z);
                acc.w = fmaf(gdh * gw[iw][3], v.w, acc.w);
            }
        }
    }

    const float gdsh = ad.gsum * ah.gsum;
    acc.x *= __frcp_rn(fmaf(gdsh, gsum_w[0], 1e-20f));
    acc.y *= __frcp_rn(fmaf(gdsh, gsum_w[1], 1e-20f));
    acc.z *= __frcp_rn(fmaf(gdsh, gsum_w[2], 1e-20f));
    acc.w *= __frcp_rn(fmaf(gdsh, gsum_w[3], 1e-20f));

    const int vidx = (d * VOL + h) * VOL + w0 + c * OUT_CH_STRIDE;
    *reinterpret_cast<float4*>(out + vidx) = acc;
}

extern "C" void kernel_launch(void* const* d_in, const int* in_sizes, int n_in,
                              void* d_out, int out_size) {
    const float* patch = (const float*)d_in[0];
    float* out = (float*)d_out;
    dim3 block(48, 2, 2);     // 48 w-groups x 2 h-rows x 2 channels = 192 threads
    dim3 grid(VOL / 2, VOL, 1);
    agg_kernel_v4c<<<grid, block>>>(patch, out);
}

// round 4
// speedup vs baseline: 1.4660x; 1.4660x over previous
#include <cuda_runtime.h>
#include <cuda_bf16.h>

// DynamicPatchAggregator — gather formulation, float4 along w, both channels
// per thread (max MLP), separable address offsets to cut register pressure.
// vol=192^3, patch=96^3, stride=48 -> starts {0,48,96}, 27 patches, C=2.
// Coverage is complete -> upsampled global branch contributes 0; skip it.
//
// addr(k, ld, lh, lw) = sd*9*PS + sh*3*PS + sw*PS + ld*9216 + lh*96 + lw
// fully separates per axis -> precompute offD[2], offH[2], offW[2].

#define VOL 192
#define PATCH 96
#define STRIDE 48
#define CH_STRIDE (PATCH*PATCH*PATCH)          // 884736
#define PATCH_STRIDE (2*CH_STRIDE)             // per-k stride (C=2)
#define OUT_CH_STRIDE (VOL*VOL*VOL)            // 7077888

__device__ __forceinline__ void axis_scalar(int x, int axis_mul,
                                            int* n, int off[2], float g[2], float* gsum) {
    int lo = (x - PATCH + STRIDE) / STRIDE; if (lo < 0) lo = 0;
    int hi = x / STRIDE; if (hi > 2) hi = 2;
    *n = hi - lo + 1;
    *gsum = 0.f;
    #pragma unroll
    for (int i = 0; i < 2; i++) {
        int si = lo + i;
        if (i < *n) {
            int l = x - si * STRIDE;
            float t = (float)(l - 48) * (1.0f / 12.0f);
            float gg = __expf(-0.5f * t * t);
            off[i] = si * axis_mul * PATCH_STRIDE + l * ((axis_mul == 9) ? (PATCH*PATCH) : PATCH);
            g[i] = gg;
            *gsum += gg;
        } else {
            off[i] = off[0];
            g[i] = 0.f;
        }
    }
}

__global__ __launch_bounds__(192, 7) void agg_kernel_v4s(const float* __restrict__ patch,
                                                         float* __restrict__ out) {
    const int w0 = threadIdx.x * 4;              // 0,4,...,188
    const int h  = blockIdx.x * 4 + threadIdx.y; // 0..191
    const int d  = blockIdx.y;                   // 0..191

    int   nd, nh;
    int   offD[2], offH[2];
    float gd[2], gh[2], gdsum, ghsum;
    axis_scalar(d, 9, &nd, offD, gd, &gdsum);
    axis_scalar(h, 3, &nh, offH, gh, &ghsum);

    // w axis: 4-wide group shares one covering set (boundaries are 48-aligned).
    int wlo = (w0 - PATCH + STRIDE) / STRIDE; if (wlo < 0) wlo = 0;
    int whi = w0 / STRIDE; if (whi > 2) whi = 2;
    const int nw = whi - wlo + 1;

    int   offW[2];
    float gw[2][4];
    #pragma unroll
    for (int i = 0; i < 2; i++) {
        int si = wlo + i;
        if (i < nw) {
            int l0 = w0 - si * STRIDE;
            offW[i] = si * PATCH_STRIDE + l0;
            #pragma unroll
            for (int j = 0; j < 4; j++) {
                float t = (float)(l0 + j - 48) * (1.0f / 12.0f);
                gw[i][j] = __expf(-0.5f * t * t);
            }
        } else {
            offW[i] = offW[0];
            #pragma unroll
            for (int j = 0; j < 4; j++) gw[i][j] = 0.f;
        }
    }

    float4 n0 = make_float4(0.f, 0.f, 0.f, 0.f);
    float4 n1 = make_float4(0.f, 0.f, 0.f, 0.f);

    #pragma unroll
    for (int id = 0; id < 2; id++) {
        if (id >= nd) break;
        #pragma unroll
        for (int ih = 0; ih < 2; ih++) {
            if (ih >= nh) break;
            const float gdh = gd[id] * gh[ih];
            const int offDH = offD[id] + offH[ih];
            #pragma unroll
            for (int iw = 0; iw < 2; iw++) {
                if (iw >= nw) break;
                const float* q = patch + offDH + offW[iw];
                const float4 v0 = __ldcs(reinterpret_cast<const float4*>(q));
                const float4 v1 = __ldcs(reinterpret_cast<const float4*>(q + CH_STRIDE));
                const float wx = gdh * gw[iw][0];
                const float wy = gdh * gw[iw][1];
                const float wz = gdh * gw[iw][2];
                const float ww = gdh * gw[iw][3];
                n0.x = fmaf(wx, v0.x, n0.x);
                n0.y = fmaf(wy, v0.y, n0.y);
                n0.z = fmaf(wz, v0.z, n0.z);
                n0.w = fmaf(ww, v0.w, n0.w);
                n1.x = fmaf(wx, v1.x, n1.x);
                n1.y = fmaf(wy, v1.y, n1.y);
                n1.z = fmaf(wz, v1.z, n1.z);
                n1.w = fmaf(ww, v1.w, n1.w);
            }
        }
    }

    const float gdsh = gdsum * ghsum;
    float4 inv;
    inv.x = __frcp_rn(fmaf(gdsh, gw[0][0] + gw[1][0], 1e-20f));
    inv.y = __frcp_rn(fmaf(gdsh, gw[0][1] + gw[1][1], 1e-20f));
    inv.z = __frcp_rn(fmaf(gdsh, gw[0][2] + gw[1][2], 1e-20f));
    inv.w = __frcp_rn(fmaf(gdsh, gw[0][3] + gw[1][3], 1e-20f));

    n0.x *= inv.x; n0.y *= inv.y; n0.z *= inv.z; n0.w *= inv.w;
    n1.x *= inv.x; n1.y *= inv.y; n1.z *= inv.z; n1.w *= inv.w;

    const int vidx = (d * VOL + h) * VOL + w0;
    __stcs(reinterpret_cast<float4*>(out + vidx), n0);
    __stcs(reinterpret_cast<float4*>(out + vidx + OUT_CH_STRIDE), n1);
}

extern "C" void kernel_launch(void* const* d_in, const int* in_sizes, int n_in,
                              void* d_out, int out_size) {
    const float* patch = (const float*)d_in[0];
    float* out = (float*)d_out;
    dim3 block(48, 4, 1);   // 48 float4-groups x 4 h-rows = 192 threads
    dim3 grid(VOL / 4, VOL, 1);
    agg_kernel_v4s<<<grid, block>>>(patch, out);
}